// round 2
// baseline (speedup 1.0000x reference)
#include <cuda_runtime.h>
#include <math.h>

// Problem constants
#define T_SEQ 256
#define BATCH 64
#define HID   512
#define G4H   2048   // 4*H
#define D2H   1024   // 2*H
#define MR    (T_SEQ*BATCH)   // 16384 rows

// ---------------- scratch (device globals: allocation-free) ----------------
__device__ float g_gxf[(size_t)MR * G4H];   // forward  gate pre-acts (x part)
__device__ float g_gxb[(size_t)MR * G4H];   // backward gate pre-acts (x part)
__device__ float g_bufA[(size_t)MR * D2H];
__device__ float g_bufB[(size_t)MR * D2H];
__device__ float g_bufC[(size_t)MR * D2H];
__device__ float g_h[2][2][BATCH * HID];    // [dir][pingpong][B*H]
__device__ float g_c[2][BATCH * HID];       // [dir][B*H]

// Buffer selectors (avoid cudaGetSymbolAddress in the capture path)
// 0 = external pointer (passed arg), 1 = g_bufA, 2 = g_bufB, 3 = g_bufC,
// 4 = g_gxf, 5 = g_gxb
__device__ __forceinline__ float* sel_buf(int sel, float* ext) {
    switch (sel) {
        case 1: return g_bufA;
        case 2: return g_bufB;
        case 3: return g_bufC;
        case 4: return g_gxf;
        case 5: return g_gxb;
        default: return ext;
    }
}
__device__ __forceinline__ const float* sel_cbuf(int sel, const float* ext) {
    switch (sel) {
        case 1: return g_bufA;
        case 2: return g_bufB;
        case 3: return g_bufC;
        case 4: return g_gxf;
        case 5: return g_gxb;
        default: return ext;
    }
}

// ---------------- GEMM: C[M,N] = A[M,K] @ W[N,K]^T + bias ----------------
// EPI=0: plain bias add (gate pre-activation)
// EPI=1: highway: g = sigmoid(logit); C = g*A + (1-g)*prev   (requires K==N)
#define BMT 128
#define BNT 128
#define BKT 16
#define SPAD 132

#define STS_TILE(s) do { \
    As[s][lk+0][lrow]    = pa0.x; As[s][lk+1][lrow]    = pa0.y; \
    As[s][lk+2][lrow]    = pa0.z; As[s][lk+3][lrow]    = pa0.w; \
    As[s][lk+0][lrow+64] = pa1.x; As[s][lk+1][lrow+64] = pa1.y; \
    As[s][lk+2][lrow+64] = pa1.z; As[s][lk+3][lrow+64] = pa1.w; \
    Ws[s][lk+0][lrow]    = pw0.x; Ws[s][lk+1][lrow]    = pw0.y; \
    Ws[s][lk+2][lrow]    = pw0.z; Ws[s][lk+3][lrow]    = pw0.w; \
    Ws[s][lk+0][lrow+64] = pw1.x; Ws[s][lk+1][lrow+64] = pw1.y; \
    Ws[s][lk+2][lrow+64] = pw1.z; Ws[s][lk+3][lrow+64] = pw1.w; } while (0)

template<int EPI>
__global__ __launch_bounds__(256, 2)
void gemm_kernel(const float* __restrict__ Aext, int aSel,
                 const float* __restrict__ W0, const float* __restrict__ W1,
                 const float* __restrict__ bias0, const float* __restrict__ bias1,
                 float* __restrict__ C0ext, int c0Sel,
                 float* __restrict__ C1ext, int c1Sel,
                 const float* __restrict__ prevExt, int prevSel,
                 int M, int N, int K)
{
    const float* A    = sel_cbuf(aSel, Aext);
    const float* W    = blockIdx.z ? W1 : W0;
    const float* bias = blockIdx.z ? bias1 : bias0;
    float*       C    = blockIdx.z ? sel_buf(c1Sel, C1ext) : sel_buf(c0Sel, C0ext);

    __shared__ float As[2][BKT][SPAD];
    __shared__ float Ws[2][BKT][SPAD];

    const int tid = threadIdx.x;
    const int tx  = tid & 15;
    const int ty  = tid >> 4;
    const int m0  = blockIdx.y * BMT;
    const int n0  = blockIdx.x * BNT;
    const int lrow = tid >> 2;          // 0..63
    const int lk   = (tid & 3) << 2;    // 0,4,8,12

    const float* Ab = A + (size_t)(m0 + lrow) * K + lk;
    const float* Wb = W + (size_t)(n0 + lrow) * K + lk;
    const size_t rstep = (size_t)64 * K;

    float4 pa0, pa1, pw0, pw1;
    pa0 = *(const float4*)(Ab);
    pa1 = *(const float4*)(Ab + rstep);
    pw0 = *(const float4*)(Wb);
    pw1 = *(const float4*)(Wb + rstep);
    STS_TILE(0);
    __syncthreads();

    float acc[8][8] = {};
    const int nk = K / BKT;
    for (int kt = 0; kt < nk; kt++) {
        const int s = kt & 1;
        if (kt + 1 < nk) {
            const int off = (kt + 1) * BKT;
            pa0 = *(const float4*)(Ab + off);
            pa1 = *(const float4*)(Ab + rstep + off);
            pw0 = *(const float4*)(Wb + off);
            pw1 = *(const float4*)(Wb + rstep + off);
        }
        #pragma unroll
        for (int k = 0; k < BKT; k++) {
            float a[8], b[8];
            *(float4*)&a[0] = *(const float4*)&As[s][k][ty * 8];
            *(float4*)&a[4] = *(const float4*)&As[s][k][ty * 8 + 4];
            *(float4*)&b[0] = *(const float4*)&Ws[s][k][tx * 8];
            *(float4*)&b[4] = *(const float4*)&Ws[s][k][tx * 8 + 4];
            #pragma unroll
            for (int i = 0; i < 8; i++)
                #pragma unroll
                for (int j = 0; j < 8; j++)
                    acc[i][j] += a[i] * b[j];
        }
        if (kt + 1 < nk) STS_TILE(s ^ 1);
        __syncthreads();
    }

    float bj[8];
    #pragma unroll
    for (int j = 0; j < 8; j++) bj[j] = bias[n0 + tx * 8 + j];

    #pragma unroll
    for (int i = 0; i < 8; i++) {
        const int m = m0 + ty * 8 + i;
        float* crow = C + (size_t)m * N + n0 + tx * 8;
        float v[8];
        if (EPI == 0) {
            #pragma unroll
            for (int j = 0; j < 8; j++) v[j] = acc[i][j] + bj[j];
        } else {
            const float* prev   = sel_cbuf(prevSel, prevExt);
            const float* catrow = A    + (size_t)m * K + n0 + tx * 8;  // K==N here
            const float* prow   = prev + (size_t)m * N + n0 + tx * 8;
            float4 c0 = *(const float4*)(catrow);
            float4 c1 = *(const float4*)(catrow + 4);
            float4 p0 = *(const float4*)(prow);
            float4 p1 = *(const float4*)(prow + 4);
            const float catv[8] = {c0.x,c0.y,c0.z,c0.w,c1.x,c1.y,c1.z,c1.w};
            const float prv[8]  = {p0.x,p0.y,p0.z,p0.w,p1.x,p1.y,p1.z,p1.w};
            #pragma unroll
            for (int j = 0; j < 8; j++) {
                float gsig = 1.f / (1.f + expf(-(acc[i][j] + bj[j])));
                v[j] = gsig * catv[j] + (1.f - gsig) * prv[j];
            }
        }
        *(float4*)(crow)     = *(float4*)&v[0];
        *(float4*)(crow + 4) = *(float4*)&v[4];
    }
}

// ---------------- LSTM recurrence step ----------------
// grid (64, 2): blockIdx.y = direction, blockIdx.x = hidden-col slice (8 cols).
// Each block computes all 4 gates for its 8 h-columns x 64 batches, then
// updates c (block-exclusive) and writes h into the ping-pong buffer + outcat.
__global__ __launch_bounds__(256)
void lstm_step_kernel(const float* __restrict__ Whf, const float* __restrict__ Whb,
                      const float* __restrict__ masks,
                      int outSel, float* __restrict__ outExt, int step)
{
    const int dir = blockIdx.y;
    const int t   = dir ? (T_SEQ - 1 - step) : step;
    const float* gx  = dir ? g_gxb : g_gxf;
    const float* Whh = dir ? Whb : Whf;
    const float* hin = g_h[dir][step & 1];
    float*      hout = g_h[dir][(step & 1) ^ 1];
    float*      c    = g_c[dir];
    float*   outcat  = sel_buf(outSel, outExt);

    const int hc0 = blockIdx.x * 8;
    const int tid = threadIdx.x;
    const int tx  = tid & 7;    // local h column
    const int ty  = tid >> 3;   // batch pair: 2*ty, 2*ty+1

    __shared__ float ws[64][36];  // [k][hc*4+gate]  (stride keeps f4 aligned)
    __shared__ float hs[64][65];  // [k][b]

    float acc[4][2] = {};

    for (int kc = 0; kc < HID; kc += 64) {
        #pragma unroll
        for (int i = 0; i < 4; i++) {
            int idx = tid + i * 256;
            int b   = idx >> 4;
            int kq  = (idx & 15) * 4;
            float4 v = *(const float4*)&hin[b * HID + kc + kq];
            hs[kq + 0][b] = v.x; hs[kq + 1][b] = v.y;
            hs[kq + 2][b] = v.z; hs[kq + 3][b] = v.w;
        }
        #pragma unroll
        for (int i = 0; i < 2; i++) {
            int idx  = tid + i * 256;
            int cidx = idx >> 4;            // 0..31 = hc*4+gate
            int kq   = (idx & 15) * 4;
            int hc   = cidx >> 2, gate = cidx & 3;
            int row  = gate * HID + hc0 + hc;
            float4 v = *(const float4*)&Whh[(size_t)row * HID + kc + kq];
            ws[kq + 0][cidx] = v.x; ws[kq + 1][cidx] = v.y;
            ws[kq + 2][cidx] = v.z; ws[kq + 3][cidx] = v.w;
        }
        __syncthreads();
        #pragma unroll 16
        for (int k = 0; k < 64; k++) {
            float4 w = *(const float4*)&ws[k][tx * 4];
            float h0 = hs[k][2 * ty];
            float h1 = hs[k][2 * ty + 1];
            acc[0][0] += w.x * h0; acc[0][1] += w.x * h1;
            acc[1][0] += w.y * h0; acc[1][1] += w.y * h1;
            acc[2][0] += w.z * h0; acc[2][1] += w.z * h1;
            acc[3][0] += w.w * h0; acc[3][1] += w.w * h1;
        }
        __syncthreads();
    }

    const int hcol = hc0 + tx;
    #pragma unroll
    for (int j = 0; j < 2; j++) {
        const int b = 2 * ty + j;
        const size_t base = (size_t)t * (BATCH * G4H) + (size_t)b * G4H;
        float pi = acc[0][j] + gx[base + 0 * HID + hcol];
        float pf = acc[1][j] + gx[base + 1 * HID + hcol];
        float pg = acc[2][j] + gx[base + 2 * HID + hcol];
        float po = acc[3][j] + gx[base + 3 * HID + hcol];
        float m  = masks[t * BATCH + b];
        const int sidx = b * HID + hcol;
        float cold = c[sidx];
        float ig = 1.f / (1.f + expf(-pi));
        float fg = 1.f / (1.f + expf(-pf));
        float og = 1.f / (1.f + expf(-po));
        float gg = tanhf(pg);
        float cn = (fg * cold + ig * gg) * m;
        float hn = og * tanhf(cn) * m;
        c[sidx]    = cn;
        hout[sidx] = hn;
        outcat[(size_t)t * (BATCH * D2H) + (size_t)b * D2H + dir * HID + hcol] = hn;
    }
}

// ---------------- small state kernels ----------------
__global__ void init_states_kernel(const float* __restrict__ f_init,
                                   const float* __restrict__ b_init, int layer)
{
    int idx = blockIdx.x * blockDim.x + threadIdx.x;
    if (idx >= BATCH * HID) return;
    int j = idx & (HID - 1);
    const float* fi = f_init + layer * 2 * HID;
    const float* bi = b_init + layer * 2 * HID;
    g_h[0][0][idx] = fi[j];
    g_c[0][idx]    = fi[HID + j];
    g_h[1][0][idx] = bi[j];
    g_c[1][idx]    = bi[HID + j];
}

__global__ void copy_states_kernel(float* __restrict__ hn, float* __restrict__ cn, int layer)
{
    int idx = blockIdx.x * blockDim.x + threadIdx.x;
    if (idx >= BATCH * HID) return;
    // after 256 steps the final h lives in pingpong slot 0
    hn[(size_t)(2 * layer + 0) * BATCH * HID + idx] = g_h[0][0][idx];
    hn[(size_t)(2 * layer + 1) * BATCH * HID + idx] = g_h[1][0][idx];
    cn[(size_t)(2 * layer + 0) * BATCH * HID + idx] = g_c[0][idx];
    cn[(size_t)(2 * layer + 1) * BATCH * HID + idx] = g_c[1][idx];
}

// ---------------- launcher ----------------
extern "C" void kernel_launch(void* const* d_in, const int* in_sizes, int n_in,
                              void* d_out, int out_size)
{
    const float* x          = (const float*)d_in[0];
    const float* masks      = (const float*)d_in[1];
    const float* f_Wih0     = (const float*)d_in[2];
    const float* f_Wih_rest = (const float*)d_in[3];
    const float* f_Whh      = (const float*)d_in[4];
    const float* f_b        = (const float*)d_in[5];
    const float* b_Wih0     = (const float*)d_in[6];
    const float* b_Wih_rest = (const float*)d_in[7];
    const float* b_Whh      = (const float*)d_in[8];
    const float* b_b        = (const float*)d_in[9];
    const float* f_init     = (const float*)d_in[10];
    const float* b_init     = (const float*)d_in[11];
    const float* proj_W     = (const float*)d_in[12];
    const float* proj_b     = (const float*)d_in[13];

    float* out = (float*)d_out;                       // [T,B,2H]
    float* hn  = out + (size_t)MR * D2H;              // [6,B,H]
    float* cn  = hn + (size_t)6 * BATCH * HID;        // [6,B,H]

    // layer input selectors:  layer0 = x (ext), layer1 = bufA, layer2 = bufC
    const int layerInSel[3]  = { 0, 1, 3 };
    // concat destination:     layer0 -> bufA, layer1 -> bufB, layer2 -> bufA
    const int catSel[3]      = { 1, 2, 1 };
    const int Kin[3]         = { 512, 1024, 1024 };

    for (int layer = 0; layer < 3; layer++) {
        init_states_kernel<<<128, 256>>>(f_init, b_init, layer);

        const float* Wf = (layer == 0) ? f_Wih0 : f_Wih_rest + (size_t)(layer - 1) * G4H * D2H;
        const float* Wb = (layer == 0) ? b_Wih0 : b_Wih_rest + (size_t)(layer - 1) * G4H * D2H;
        dim3 ggrid(G4H / BNT, MR / BMT, 2);
        gemm_kernel<0><<<ggrid, 256>>>(
            (layer == 0) ? x : nullptr, layerInSel[layer],
            Wf, Wb,
            f_b + (size_t)layer * G4H, b_b + (size_t)layer * G4H,
            nullptr, 4 /*gxf*/, nullptr, 5 /*gxb*/,
            nullptr, 0,
            MR, G4H, Kin[layer]);

        const float* Whf = f_Whh + (size_t)layer * G4H * HID;
        const float* Whb = b_Whh + (size_t)layer * G4H * HID;
        for (int s = 0; s < T_SEQ; s++) {
            lstm_step_kernel<<<dim3(64, 2), 256>>>(Whf, Whb, masks,
                                                   catSel[layer], nullptr, s);
        }

        copy_states_kernel<<<128, 256>>>(hn, cn, layer);

        if (layer > 0) {
            // highway:  dst = (layer==1) ? bufC : out ;  prev = layer input
            dim3 pgrid(D2H / BNT, MR / BMT, 1);
            gemm_kernel<1><<<pgrid, 256>>>(
                nullptr, catSel[layer],
                proj_W + (size_t)(layer - 1) * D2H * D2H, nullptr,
                proj_b + (size_t)(layer - 1) * D2H, nullptr,
                (layer == 2) ? out : nullptr, (layer == 1) ? 3 : 0,
                nullptr, 0,
                (layer == 0) ? nullptr : ((layer == 1) ? nullptr : nullptr), layerInSel[layer],
                MR, D2H, D2H);
        }
    }
}

// round 3
// speedup vs baseline: 1.2748x; 1.2748x over previous
#include <cuda_runtime.h>
#include <math.h>

// Problem constants
#define T_SEQ 256
#define BATCH 64
#define HID   512
#define G4H   2048   // 4*H
#define D2H   1024   // 2*H
#define MR    (T_SEQ*BATCH)   // 16384 rows
#define NBLK_DIR 64

typedef unsigned long long u64;

// ---------------- scratch (device globals: allocation-free) ----------------
__device__ float g_gxf[(size_t)MR * G4H];   // forward  gate pre-acts (x part)
__device__ float g_gxb[(size_t)MR * G4H];   // backward gate pre-acts (x part)
__device__ float g_bufA[(size_t)MR * D2H];
__device__ float g_bufB[(size_t)MR * D2H];
__device__ float g_bufC[(size_t)MR * D2H];
__device__ float g_h[2][2][BATCH * HID];    // [dir][pingpong][B*H]
__device__ float g_c[2][BATCH * HID];       // [dir][B*H]
__device__ unsigned g_bar[2];               // per-direction grid barrier counters

// Buffer selectors (no cudaGetSymbolAddress in the capture path)
__device__ __forceinline__ float* sel_buf(int sel, float* ext) {
    switch (sel) {
        case 1: return g_bufA;
        case 2: return g_bufB;
        case 3: return g_bufC;
        case 4: return g_gxf;
        case 5: return g_gxb;
        default: return ext;
    }
}
__device__ __forceinline__ const float* sel_cbuf(int sel, const float* ext) {
    switch (sel) {
        case 1: return g_bufA;
        case 2: return g_bufB;
        case 3: return g_bufC;
        case 4: return g_gxf;
        case 5: return g_gxb;
        default: return ext;
    }
}

// ---------------- packed f32x2 helpers ----------------
__device__ __forceinline__ u64 pack2(float lo, float hi) {
    u64 r; asm("mov.b64 %0, {%1, %2};" : "=l"(r) : "f"(lo), "f"(hi)); return r;
}
__device__ __forceinline__ void unpack2(u64 v, float& lo, float& hi) {
    asm("mov.b64 {%0, %1}, %2;" : "=f"(lo), "=f"(hi) : "l"(v));
}
__device__ __forceinline__ void ffma2(u64& d, u64 a, u64 b) {
    asm("fma.rn.f32x2 %0, %1, %2, %0;" : "+l"(d) : "l"(a), "l"(b));
}

__device__ __forceinline__ float sigf(float x) { return 1.f / (1.f + expf(-x)); }

// ---------------- GEMM: C[M,N] = A[M,K] @ W[N,K]^T + bias ----------------
#define BMT 128
#define BNT 128
#define BKT 16
#define SPAD 132

#define STS_TILE(s) do { \
    As[s][lk+0][lrow]    = pa0.x; As[s][lk+1][lrow]    = pa0.y; \
    As[s][lk+2][lrow]    = pa0.z; As[s][lk+3][lrow]    = pa0.w; \
    As[s][lk+0][lrow+64] = pa1.x; As[s][lk+1][lrow+64] = pa1.y; \
    As[s][lk+2][lrow+64] = pa1.z; As[s][lk+3][lrow+64] = pa1.w; \
    Ws[s][lk+0][lrow]    = pw0.x; Ws[s][lk+1][lrow]    = pw0.y; \
    Ws[s][lk+2][lrow]    = pw0.z; Ws[s][lk+3][lrow]    = pw0.w; \
    Ws[s][lk+0][lrow+64] = pw1.x; Ws[s][lk+1][lrow+64] = pw1.y; \
    Ws[s][lk+2][lrow+64] = pw1.z; Ws[s][lk+3][lrow+64] = pw1.w; } while (0)

template<int EPI>
__global__ __launch_bounds__(256, 2)
void gemm_kernel(const float* __restrict__ Aext, int aSel,
                 const float* __restrict__ W0, const float* __restrict__ W1,
                 const float* __restrict__ bias0, const float* __restrict__ bias1,
                 float* __restrict__ C0ext, int c0Sel,
                 float* __restrict__ C1ext, int c1Sel,
                 const float* __restrict__ prevExt, int prevSel,
                 int M, int N, int K)
{
    const float* A    = sel_cbuf(aSel, Aext);
    const float* W    = blockIdx.z ? W1 : W0;
    const float* bias = blockIdx.z ? bias1 : bias0;
    float*       C    = blockIdx.z ? sel_buf(c1Sel, C1ext) : sel_buf(c0Sel, C0ext);

    __shared__ float As[2][BKT][SPAD];
    __shared__ float Ws[2][BKT][SPAD];

    const int tid = threadIdx.x;
    const int tx  = tid & 15;
    const int ty  = tid >> 4;
    const int m0  = blockIdx.y * BMT;
    const int n0  = blockIdx.x * BNT;
    const int lrow = tid >> 2;          // 0..63
    const int lk   = (tid & 3) << 2;    // 0,4,8,12

    const float* Ab = A + (size_t)(m0 + lrow) * K + lk;
    const float* Wb = W + (size_t)(n0 + lrow) * K + lk;
    const size_t rstep = (size_t)64 * K;

    float4 pa0, pa1, pw0, pw1;
    pa0 = *(const float4*)(Ab);
    pa1 = *(const float4*)(Ab + rstep);
    pw0 = *(const float4*)(Wb);
    pw1 = *(const float4*)(Wb + rstep);
    STS_TILE(0);
    __syncthreads();

    float acc[8][8] = {};
    const int nk = K / BKT;
    for (int kt = 0; kt < nk; kt++) {
        const int s = kt & 1;
        if (kt + 1 < nk) {
            const int off = (kt + 1) * BKT;
            pa0 = *(const float4*)(Ab + off);
            pa1 = *(const float4*)(Ab + rstep + off);
            pw0 = *(const float4*)(Wb + off);
            pw1 = *(const float4*)(Wb + rstep + off);
        }
        #pragma unroll
        for (int k = 0; k < BKT; k++) {
            float a[8], b[8];
            *(float4*)&a[0] = *(const float4*)&As[s][k][ty * 8];
            *(float4*)&a[4] = *(const float4*)&As[s][k][ty * 8 + 4];
            *(float4*)&b[0] = *(const float4*)&Ws[s][k][tx * 8];
            *(float4*)&b[4] = *(const float4*)&Ws[s][k][tx * 8 + 4];
            #pragma unroll
            for (int i = 0; i < 8; i++)
                #pragma unroll
                for (int j = 0; j < 8; j++)
                    acc[i][j] += a[i] * b[j];
        }
        if (kt + 1 < nk) STS_TILE(s ^ 1);
        __syncthreads();
    }

    float bj[8];
    #pragma unroll
    for (int j = 0; j < 8; j++) bj[j] = bias[n0 + tx * 8 + j];

    #pragma unroll
    for (int i = 0; i < 8; i++) {
        const int m = m0 + ty * 8 + i;
        float* crow = C + (size_t)m * N + n0 + tx * 8;
        float v[8];
        if (EPI == 0) {
            #pragma unroll
            for (int j = 0; j < 8; j++) v[j] = acc[i][j] + bj[j];
        } else {
            const float* prev   = sel_cbuf(prevSel, prevExt);
            const float* catrow = A    + (size_t)m * K + n0 + tx * 8;  // K==N here
            const float* prow   = prev + (size_t)m * N + n0 + tx * 8;
            float4 c0 = *(const float4*)(catrow);
            float4 c1 = *(const float4*)(catrow + 4);
            float4 p0 = *(const float4*)(prow);
            float4 p1 = *(const float4*)(prow + 4);
            const float catv[8] = {c0.x,c0.y,c0.z,c0.w,c1.x,c1.y,c1.z,c1.w};
            const float prv[8]  = {p0.x,p0.y,p0.z,p0.w,p1.x,p1.y,p1.z,p1.w};
            #pragma unroll
            for (int j = 0; j < 8; j++) {
                float gsig = 1.f / (1.f + expf(-(acc[i][j] + bj[j])));
                v[j] = gsig * catv[j] + (1.f - gsig) * prv[j];
            }
        }
        *(float4*)(crow)     = *(float4*)&v[0];
        *(float4*)(crow + 4) = *(float4*)&v[4];
    }
}

// ---------------- persistent LSTM recurrence (one launch per layer) --------
// grid (64, 2): blockIdx.y = direction, blockIdx.x = 8-column slice.
// Whh slice stays in smem across all 256 steps; c state stays in registers;
// h exchanged via global ping-pong + per-direction grid barrier.
#define WS_F4   (HID * 8)            // 4096 float4 = 16384 floats (64KB)
#define HS_STRIDE 66
#define HS_FLOATS (64 * HS_STRIDE)   // one h chunk buffer

__global__ __launch_bounds__(256, 1)
void pers_lstm_kernel(const float* __restrict__ Whf, const float* __restrict__ Whb,
                      const float* __restrict__ masks,
                      const float* __restrict__ f_init, const float* __restrict__ b_init,
                      int layer, int outSel, float* __restrict__ outExt)
{
    extern __shared__ float smem[];
    float* wsm  = smem;                       // [512][32] floats
    float* hsm0 = smem + WS_F4 * 4;           // chunk buffer 0: [64][66]
    float* hsm1 = hsm0 + HS_FLOATS;           // chunk buffer 1

    const int dir  = blockIdx.y;
    const float* Whh  = dir ? Whb : Whf;
    const float* gx   = dir ? g_gxb : g_gxf;
    const float* init = (dir ? b_init : f_init) + (size_t)layer * 2 * HID;
    float* outcat = sel_buf(outSel, outExt);

    const int tid = threadIdx.x;
    const int tx  = tid & 7;     // local column 0..7
    const int ty  = tid >> 3;    // batch pair index 0..31
    const int hc0 = blockIdx.x * 8;
    const int hcol = hc0 + tx;
    const int b0 = 2 * ty, b1 = 2 * ty + 1;

    // ---- load this block's Whh slice into smem (once per layer) ----
    // wsm[k*32 + col*4 + gate] = Whh[(gate*HID + hc0+col)*HID + k]
    for (int col = 0; col < 8; col++) {
        #pragma unroll
        for (int g = 0; g < 4; g++) {
            const float* src = Whh + (size_t)(g * HID + hc0 + col) * HID;
            for (int k = tid; k < HID; k += 256)
                wsm[k * 32 + col * 4 + g] = src[k];
        }
    }

    // c state in registers (broadcast init, identical for every batch)
    float creg0 = init[HID + hcol];
    float creg1 = creg0;
    __syncthreads();

    const ulonglong2* wq = (const ulonglong2*)wsm;

    for (int s = 0; s < T_SEQ; s++) {
        const int t = dir ? (T_SEQ - 1 - s) : s;
        const float* hin = g_h[dir][s & 1];
        float* hout      = g_h[dir][(s & 1) ^ 1];

        // hoisted gx + mask loads (independent of h, hide L2 latency)
        const size_t gb0 = ((size_t)t * BATCH + b0) * G4H;
        const size_t gb1 = ((size_t)t * BATCH + b1) * G4H;
        float gxi0 = __ldg(&gx[gb0 + 0*HID + hcol]);
        float gxf0 = __ldg(&gx[gb0 + 1*HID + hcol]);
        float gxg0 = __ldg(&gx[gb0 + 2*HID + hcol]);
        float gxo0 = __ldg(&gx[gb0 + 3*HID + hcol]);
        float gxi1 = __ldg(&gx[gb1 + 0*HID + hcol]);
        float gxf1 = __ldg(&gx[gb1 + 1*HID + hcol]);
        float gxg1 = __ldg(&gx[gb1 + 2*HID + hcol]);
        float gxo1 = __ldg(&gx[gb1 + 3*HID + hcol]);
        float m0 = __ldg(&masks[t * BATCH + b0]);
        float m1 = __ldg(&masks[t * BATCH + b1]);

        u64 aif0 = 0, ago0 = 0, aif1 = 0, ago1 = 0;  // (0.f,0.f) bit pattern

        // prefetch h chunk 0 (must bypass L1: stale across steps)
        float4 pf[4];
        #pragma unroll
        for (int i = 0; i < 4; i++) {
            int idx = tid + i * 256;
            pf[i] = __ldcg((const float4*)&hin[(idx >> 4) * HID + ((idx & 15) << 2)]);
        }

        for (int kc = 0; kc < 8; kc++) {
            float* hs = (kc & 1) ? hsm1 : hsm0;
            #pragma unroll
            for (int i = 0; i < 4; i++) {
                int idx = tid + i * 256;
                int bb = idx >> 4, kq = (idx & 15) << 2;
                hs[(kq + 0) * HS_STRIDE + bb] = pf[i].x;
                hs[(kq + 1) * HS_STRIDE + bb] = pf[i].y;
                hs[(kq + 2) * HS_STRIDE + bb] = pf[i].z;
                hs[(kq + 3) * HS_STRIDE + bb] = pf[i].w;
            }
            __syncthreads();
            if (kc < 7) {
                #pragma unroll
                for (int i = 0; i < 4; i++) {
                    int idx = tid + i * 256;
                    pf[i] = __ldcg((const float4*)&hin[(idx >> 4) * HID + (kc + 1) * 64 + ((idx & 15) << 2)]);
                }
            }
            const int kbase = kc * 64;
            #pragma unroll 16
            for (int k = 0; k < 64; k++) {
                ulonglong2 w = wq[(kbase + k) * 8 + tx];     // (wi,wf),(wg,wo)
                float2 hp = *(const float2*)&hs[k * HS_STRIDE + b0];  // (h_b0, h_b1)
                u64 hd0 = pack2(hp.x, hp.x);
                u64 hd1 = pack2(hp.y, hp.y);
                ffma2(aif0, w.x, hd0);
                ffma2(ago0, w.y, hd0);
                ffma2(aif1, w.x, hd1);
                ffma2(ago1, w.y, hd1);
            }
            // next iteration's store targets the other buffer; the per-chunk
            // __syncthreads above orders store->read and read->overwrite.
        }

        // ---- epilogue: gates -> c,h update ----
        float ai0, af0, ag0, ao0, ai1, af1, ag1, ao1;
        unpack2(aif0, ai0, af0); unpack2(ago0, ag0, ao0);
        unpack2(aif1, ai1, af1); unpack2(ago1, ag1, ao1);

        {
            float ig = sigf(ai0 + gxi0), fg = sigf(af0 + gxf0);
            float gg = tanhf(ag0 + gxg0), og = sigf(ao0 + gxo0);
            float cn = (fg * creg0 + ig * gg) * m0;
            float hn = og * tanhf(cn) * m0;
            creg0 = cn;
            hout[b0 * HID + hcol] = hn;
            outcat[(size_t)t * (BATCH * D2H) + (size_t)b0 * D2H + dir * HID + hcol] = hn;
        }
        {
            float ig = sigf(ai1 + gxi1), fg = sigf(af1 + gxf1);
            float gg = tanhf(ag1 + gxg1), og = sigf(ao1 + gxo1);
            float cn = (fg * creg1 + ig * gg) * m1;
            float hn = og * tanhf(cn) * m1;
            creg1 = cn;
            hout[b1 * HID + hcol] = hn;
            outcat[(size_t)t * (BATCH * D2H) + (size_t)b1 * D2H + dir * HID + hcol] = hn;
        }

        // ---- per-direction grid barrier ----
        __threadfence();       // make h stores visible at gpu scope
        __syncthreads();       // all threads of block arrived + fenced
        if (tid == 0) {
            atomicAdd(&g_bar[dir], 1u);
            const unsigned target = (unsigned)NBLK_DIR * (unsigned)(s + 1);
            volatile unsigned* p = &g_bar[dir];
            while (*p < target) __nanosleep(64);
        }
        __syncthreads();
    }

    // write final c state (final h is already in g_h[dir][0])
    g_c[dir][b0 * HID + hcol] = creg0;
    g_c[dir][b1 * HID + hcol] = creg1;
}

// ---------------- small state kernels ----------------
__global__ void init_states_kernel(const float* __restrict__ f_init,
                                   const float* __restrict__ b_init, int layer)
{
    int idx = blockIdx.x * blockDim.x + threadIdx.x;
    if (idx < 2 && blockIdx.x == 0) g_bar[idx] = 0;   // reset grid barrier counters
    if (idx >= BATCH * HID) return;
    int j = idx & (HID - 1);
    const float* fi = f_init + layer * 2 * HID;
    const float* bi = b_init + layer * 2 * HID;
    g_h[0][0][idx] = fi[j];
    g_c[0][idx]    = fi[HID + j];
    g_h[1][0][idx] = bi[j];
    g_c[1][idx]    = bi[HID + j];
}

__global__ void copy_states_kernel(float* __restrict__ hn, float* __restrict__ cn, int layer)
{
    int idx = blockIdx.x * blockDim.x + threadIdx.x;
    if (idx >= BATCH * HID) return;
    hn[(size_t)(2 * layer + 0) * BATCH * HID + idx] = g_h[0][0][idx];
    hn[(size_t)(2 * layer + 1) * BATCH * HID + idx] = g_h[1][0][idx];
    cn[(size_t)(2 * layer + 0) * BATCH * HID + idx] = g_c[0][idx];
    cn[(size_t)(2 * layer + 1) * BATCH * HID + idx] = g_c[1][idx];
}

// ---------------- launcher ----------------
extern "C" void kernel_launch(void* const* d_in, const int* in_sizes, int n_in,
                              void* d_out, int out_size)
{
    const float* x          = (const float*)d_in[0];
    const float* masks      = (const float*)d_in[1];
    const float* f_Wih0     = (const float*)d_in[2];
    const float* f_Wih_rest = (const float*)d_in[3];
    const float* f_Whh      = (const float*)d_in[4];
    const float* f_b        = (const float*)d_in[5];
    const float* b_Wih0     = (const float*)d_in[6];
    const float* b_Wih_rest = (const float*)d_in[7];
    const float* b_Whh      = (const float*)d_in[8];
    const float* b_b        = (const float*)d_in[9];
    const float* f_init     = (const float*)d_in[10];
    const float* b_init     = (const float*)d_in[11];
    const float* proj_W     = (const float*)d_in[12];
    const float* proj_b     = (const float*)d_in[13];

    float* out = (float*)d_out;                       // [T,B,2H]
    float* hn  = out + (size_t)MR * D2H;              // [6,B,H]
    float* cn  = hn + (size_t)6 * BATCH * HID;        // [6,B,H]

    // persistent kernel needs >48KB dynamic smem
    const int pers_smem = (WS_F4 * 4 + 2 * HS_FLOATS) * (int)sizeof(float);
    cudaFuncSetAttribute(pers_lstm_kernel,
                         cudaFuncAttributeMaxDynamicSharedMemorySize, pers_smem);

    // layer input selectors:  layer0 = x (ext), layer1 = bufA, layer2 = bufC
    const int layerInSel[3]  = { 0, 1, 3 };
    // concat destination:     layer0 -> bufA, layer1 -> bufB, layer2 -> bufA
    const int catSel[3]      = { 1, 2, 1 };
    const int Kin[3]         = { 512, 1024, 1024 };

    for (int layer = 0; layer < 3; layer++) {
        init_states_kernel<<<128, 256>>>(f_init, b_init, layer);

        const float* Wf = (layer == 0) ? f_Wih0 : f_Wih_rest + (size_t)(layer - 1) * G4H * D2H;
        const float* Wb = (layer == 0) ? b_Wih0 : b_Wih_rest + (size_t)(layer - 1) * G4H * D2H;
        dim3 ggrid(G4H / BNT, MR / BMT, 2);
        gemm_kernel<0><<<ggrid, 256>>>(
            (layer == 0) ? x : nullptr, layerInSel[layer],
            Wf, Wb,
            f_b + (size_t)layer * G4H, b_b + (size_t)layer * G4H,
            nullptr, 4 /*gxf*/, nullptr, 5 /*gxb*/,
            nullptr, 0,
            MR, G4H, Kin[layer]);

        const float* Whf = f_Whh + (size_t)layer * G4H * HID;
        const float* Whb = b_Whh + (size_t)layer * G4H * HID;
        pers_lstm_kernel<<<dim3(NBLK_DIR, 2), 256, pers_smem>>>(
            Whf, Whb, masks, f_init, b_init, layer, catSel[layer], nullptr);

        copy_states_kernel<<<128, 256>>>(hn, cn, layer);

        if (layer > 0) {
            dim3 pgrid(D2H / BNT, MR / BMT, 1);
            gemm_kernel<1><<<pgrid, 256>>>(
                nullptr, catSel[layer],
                proj_W + (size_t)(layer - 1) * D2H * D2H, nullptr,
                proj_b + (size_t)(layer - 1) * D2H, nullptr,
                (layer == 2) ? out : nullptr, (layer == 1) ? 3 : 0,
                nullptr, 0,
                nullptr, layerInSel[layer],
                MR, D2H, D2H);
        }
    }
}

// round 4
// speedup vs baseline: 1.2762x; 1.0011x over previous
#include <cuda_runtime.h>
#include <math.h>

// Problem constants
#define T_SEQ 256
#define BATCH 64
#define HID   512
#define G4H   2048   // 4*H
#define D2H   1024   // 2*H
#define MR    (T_SEQ*BATCH)   // 16384 rows
#define NBLK_DIR 64

typedef unsigned long long u64;

// ---------------- scratch (device globals: allocation-free) ----------------
__device__ float g_gxf[(size_t)MR * G4H];
__device__ float g_gxb[(size_t)MR * G4H];
__device__ float g_bufA[(size_t)MR * D2H];
__device__ float g_bufB[(size_t)MR * D2H];
__device__ float g_bufC[(size_t)MR * D2H];
__device__ float g_h[2][2][BATCH * HID];    // [dir][pingpong][B*H]
__device__ float g_c[2][BATCH * HID];       // [dir][B*H]
__device__ unsigned g_bar[2];               // per-direction grid barrier counters

__device__ __forceinline__ float* sel_buf(int sel, float* ext) {
    switch (sel) {
        case 1: return g_bufA;
        case 2: return g_bufB;
        case 3: return g_bufC;
        case 4: return g_gxf;
        case 5: return g_gxb;
        default: return ext;
    }
}
__device__ __forceinline__ const float* sel_cbuf(int sel, const float* ext) {
    switch (sel) {
        case 1: return g_bufA;
        case 2: return g_bufB;
        case 3: return g_bufC;
        case 4: return g_gxf;
        case 5: return g_gxb;
        default: return ext;
    }
}

// ---------------- packed f32x2 helpers ----------------
__device__ __forceinline__ u64 pack2(float lo, float hi) {
    u64 r; asm("mov.b64 %0, {%1, %2};" : "=l"(r) : "f"(lo), "f"(hi)); return r;
}
__device__ __forceinline__ void unpack2(u64 v, float& lo, float& hi) {
    asm("mov.b64 {%0, %1}, %2;" : "=f"(lo), "=f"(hi) : "l"(v));
}
__device__ __forceinline__ void ffma2(u64& d, u64 a, u64 b) {
    asm("fma.rn.f32x2 %0, %1, %2, %0;" : "+l"(d) : "l"(a), "l"(b));
}
__device__ __forceinline__ u64 addf2(u64 a, u64 b) {
    u64 r; asm("add.rn.f32x2 %0, %1, %2;" : "=l"(r) : "l"(a), "l"(b)); return r;
}

__device__ __forceinline__ float sigf(float x) { return 1.f / (1.f + __expf(-x)); }

// ---------------- GEMM: C[M,N] = A[M,K] @ W[N,K]^T + bias ----------------
#define BMT 128
#define BNT 128
#define BKT 16
#define SPAD 132

#define STS_TILE(s) do { \
    As[s][lk+0][lrow]    = pa0.x; As[s][lk+1][lrow]    = pa0.y; \
    As[s][lk+2][lrow]    = pa0.z; As[s][lk+3][lrow]    = pa0.w; \
    As[s][lk+0][lrow+64] = pa1.x; As[s][lk+1][lrow+64] = pa1.y; \
    As[s][lk+2][lrow+64] = pa1.z; As[s][lk+3][lrow+64] = pa1.w; \
    Ws[s][lk+0][lrow]    = pw0.x; Ws[s][lk+1][lrow]    = pw0.y; \
    Ws[s][lk+2][lrow]    = pw0.z; Ws[s][lk+3][lrow]    = pw0.w; \
    Ws[s][lk+0][lrow+64] = pw1.x; Ws[s][lk+1][lrow+64] = pw1.y; \
    Ws[s][lk+2][lrow+64] = pw1.z; Ws[s][lk+3][lrow+64] = pw1.w; } while (0)

template<int EPI>
__global__ __launch_bounds__(256, 2)
void gemm_kernel(const float* __restrict__ Aext, int aSel,
                 const float* __restrict__ W0, const float* __restrict__ W1,
                 const float* __restrict__ bias0, const float* __restrict__ bias1,
                 float* __restrict__ C0ext, int c0Sel,
                 float* __restrict__ C1ext, int c1Sel,
                 const float* __restrict__ prevExt, int prevSel,
                 int M, int N, int K)
{
    const float* A    = sel_cbuf(aSel, Aext);
    const float* W    = blockIdx.z ? W1 : W0;
    const float* bias = blockIdx.z ? bias1 : bias0;
    float*       C    = blockIdx.z ? sel_buf(c1Sel, C1ext) : sel_buf(c0Sel, C0ext);

    __shared__ float As[2][BKT][SPAD];
    __shared__ float Ws[2][BKT][SPAD];

    const int tid = threadIdx.x;
    const int tx  = tid & 15;
    const int ty  = tid >> 4;
    const int m0  = blockIdx.y * BMT;
    const int n0  = blockIdx.x * BNT;
    const int lrow = tid >> 2;
    const int lk   = (tid & 3) << 2;

    const float* Ab = A + (size_t)(m0 + lrow) * K + lk;
    const float* Wb = W + (size_t)(n0 + lrow) * K + lk;
    const size_t rstep = (size_t)64 * K;

    float4 pa0, pa1, pw0, pw1;
    pa0 = *(const float4*)(Ab);
    pa1 = *(const float4*)(Ab + rstep);
    pw0 = *(const float4*)(Wb);
    pw1 = *(const float4*)(Wb + rstep);
    STS_TILE(0);
    __syncthreads();

    float acc[8][8] = {};
    const int nk = K / BKT;
    for (int kt = 0; kt < nk; kt++) {
        const int s = kt & 1;
        if (kt + 1 < nk) {
            const int off = (kt + 1) * BKT;
            pa0 = *(const float4*)(Ab + off);
            pa1 = *(const float4*)(Ab + rstep + off);
            pw0 = *(const float4*)(Wb + off);
            pw1 = *(const float4*)(Wb + rstep + off);
        }
        #pragma unroll
        for (int k = 0; k < BKT; k++) {
            float a[8], b[8];
            *(float4*)&a[0] = *(const float4*)&As[s][k][ty * 8];
            *(float4*)&a[4] = *(const float4*)&As[s][k][ty * 8 + 4];
            *(float4*)&b[0] = *(const float4*)&Ws[s][k][tx * 8];
            *(float4*)&b[4] = *(const float4*)&Ws[s][k][tx * 8 + 4];
            #pragma unroll
            for (int i = 0; i < 8; i++)
                #pragma unroll
                for (int j = 0; j < 8; j++)
                    acc[i][j] += a[i] * b[j];
        }
        if (kt + 1 < nk) STS_TILE(s ^ 1);
        __syncthreads();
    }

    float bj[8];
    #pragma unroll
    for (int j = 0; j < 8; j++) bj[j] = bias[n0 + tx * 8 + j];

    #pragma unroll
    for (int i = 0; i < 8; i++) {
        const int m = m0 + ty * 8 + i;
        float* crow = C + (size_t)m * N + n0 + tx * 8;
        float v[8];
        if (EPI == 0) {
            #pragma unroll
            for (int j = 0; j < 8; j++) v[j] = acc[i][j] + bj[j];
        } else {
            const float* prev   = sel_cbuf(prevSel, prevExt);
            const float* catrow = A    + (size_t)m * K + n0 + tx * 8;  // K==N here
            const float* prow   = prev + (size_t)m * N + n0 + tx * 8;
            float4 c0 = *(const float4*)(catrow);
            float4 c1 = *(const float4*)(catrow + 4);
            float4 p0 = *(const float4*)(prow);
            float4 p1 = *(const float4*)(prow + 4);
            const float catv[8] = {c0.x,c0.y,c0.z,c0.w,c1.x,c1.y,c1.z,c1.w};
            const float prv[8]  = {p0.x,p0.y,p0.z,p0.w,p1.x,p1.y,p1.z,p1.w};
            #pragma unroll
            for (int j = 0; j < 8; j++) {
                float gsig = 1.f / (1.f + expf(-(acc[i][j] + bj[j])));
                v[j] = gsig * catv[j] + (1.f - gsig) * prv[j];
            }
        }
        *(float4*)(crow)     = *(float4*)&v[0];
        *(float4*)(crow + 4) = *(float4*)&v[4];
    }
}

// ---------------- persistent LSTM recurrence (one launch per layer) --------
// grid (64, 2), 512 threads. Block owns 8 hidden cols (all 4 gates, 64 batches).
// 16 warps = (colpair p in 0..3) x (batch-half bh) x (k-half kh).
// Weight loads are warp-uniform LDS.128 (broadcast); h loads are conflict-free
// LDS.32 (stride 513). Partials over k-halves merged via smem + add.f32x2.
#define HS_ST   513
#define SM_W_FLOATS   (8 * HID * 4)                 // 16384 floats (64KB)
#define SM_H_FLOATS   (BATCH * HS_ST)               // 32832 floats
#define SM_RED_U64    (8 * 32 * 4)                  // 1024 u64 (8KB)
#define PERS_SMEM_BYTES ((SM_W_FLOATS + SM_H_FLOATS) * 4 + SM_RED_U64 * 8)

__global__ __launch_bounds__(512, 1)
void pers_lstm_kernel(const float* __restrict__ Whf, const float* __restrict__ Whb,
                      const float* __restrict__ masks,
                      const float* __restrict__ f_init, const float* __restrict__ b_init,
                      int layer, int outSel, float* __restrict__ outExt)
{
    extern __shared__ float smem[];
    float* wsm = smem;                               // [col][k][gate] float
    float* hs  = smem + SM_W_FLOATS;                 // [b*513 + k]
    u64*   red = (u64*)(smem + SM_W_FLOATS + SM_H_FLOATS);

    const int dir  = blockIdx.y;
    const float* Whh  = dir ? Whb : Whf;
    const float* gx   = dir ? g_gxb : g_gxf;
    const float* init = (dir ? b_init : f_init) + (size_t)layer * 2 * HID;
    float* outcat = sel_buf(outSel, outExt);

    const int tid  = threadIdx.x;
    const int lane = tid & 31;
    const int wid  = tid >> 5;
    const int hc0  = blockIdx.x * 8;

    // warp roles
    const int kh  = wid >> 3;          // k half
    const int wlo = wid & 7;
    const int p   = wlo & 3;           // column pair (cols 2p, 2p+1)
    const int bh  = wlo >> 2;          // batch half
    const int b   = bh * 32 + lane;    // this thread's batch
    const int hcol0 = hc0 + 2 * p;     // first of this thread's two columns

    // staging role (all threads)
    const int sb  = tid >> 3;          // batch 0..63
    const int skq = (tid & 7) << 2;    // k quad 0,4,...,28

    // ---- load Whh slice into smem once: wsm[(c*512 + k)*4 + g] ----
    #pragma unroll
    for (int c = 0; c < 8; c++)
        #pragma unroll
        for (int g = 0; g < 4; g++)
            wsm[((c << 9) + tid) * 4 + g] = Whh[(size_t)((g << 9) + hc0 + c) * HID + tid];

    // c state in registers (broadcast init, identical per batch)
    float creg0 = init[HID + hcol0];
    float creg1 = init[HID + hcol0 + 1];
    __syncthreads();

    const ulonglong2* wq  = (const ulonglong2*)wsm;
    const ulonglong2* wq0 = wq + (2 * p) * HID;
    const ulonglong2* wq1 = wq + (2 * p + 1) * HID;
    const float* hrowc = hs + b * HS_ST;
    const int   k0 = kh * 256;

    for (int s = 0; s < T_SEQ; s++) {
        const int t = dir ? (T_SEQ - 1 - s) : s;
        const float* hin = g_h[dir][s & 1];
        float* hout      = g_h[dir][(s & 1) ^ 1];

        // ---- prefetch gx + mask for this step (kh==0 warps only) ----
        float2 gi, gf, gg, go; float mk = 0.f;
        if (kh == 0) {
            const size_t gb = ((size_t)t * BATCH + b) * G4H + hcol0;
            gi = __ldcg((const float2*)&gx[gb + 0 * HID]);
            gf = __ldcg((const float2*)&gx[gb + 1 * HID]);
            gg = __ldcg((const float2*)&gx[gb + 2 * HID]);
            go = __ldcg((const float2*)&gx[gb + 3 * HID]);
            mk = __ldg(&masks[t * BATCH + b]);
        }

        // ---- stage full h into smem (coalesced LDG.128, conflict-free STS) ----
        const float* hrow = hin + sb * HID + skq;
        float* hdstb = hs + sb * HS_ST + skq;
        #pragma unroll
        for (int half = 0; half < 2; half++) {
            float4 pf[8];
            #pragma unroll
            for (int i = 0; i < 8; i++)
                pf[i] = __ldcg((const float4*)(hrow + half * 256 + i * 32));
            #pragma unroll
            for (int i = 0; i < 8; i++) {
                float* d = hdstb + half * 256 + i * 32;
                d[0] = pf[i].x; d[1] = pf[i].y; d[2] = pf[i].z; d[3] = pf[i].w;
            }
        }
        __syncthreads();

        // ---- main accumulation over this warp's k half ----
        u64 a0 = 0, a1 = 0, a2 = 0, a3 = 0;  // (i,f)c0 (g,o)c0 (i,f)c1 (g,o)c1
        #pragma unroll 8
        for (int k = k0; k < k0 + 256; k++) {
            ulonglong2 wa = wq0[k];          // uniform LDS.128
            ulonglong2 wb = wq1[k];          // uniform LDS.128
            float hv = hrowc[k];             // conflict-free LDS.32
            u64 hd = pack2(hv, hv);
            ffma2(a0, wa.x, hd);
            ffma2(a1, wa.y, hd);
            ffma2(a2, wb.x, hd);
            ffma2(a3, wb.y, hd);
        }

        // ---- k-half reduction ----
        if (kh == 1) {
            ulonglong2* r = (ulonglong2*)(red + (((wlo << 5) + lane) << 2));
            r[0] = make_ulonglong2(a0, a1);
            r[1] = make_ulonglong2(a2, a3);
        }
        __syncthreads();

        if (kh == 0) {
            const ulonglong2* r = (const ulonglong2*)(red + (((wlo << 5) + lane) << 2));
            ulonglong2 r0 = r[0], r1 = r[1];
            a0 = addf2(a0, r0.x); a1 = addf2(a1, r0.y);
            a2 = addf2(a2, r1.x); a3 = addf2(a3, r1.y);

            float pi0, pF0, pg0, po0, pi1, pF1, pg1, po1;
            unpack2(a0, pi0, pF0); unpack2(a1, pg0, po0);
            unpack2(a2, pi1, pF1); unpack2(a3, pg1, po1);

            float ig0 = sigf(pi0 + gi.x), fg0 = sigf(pF0 + gf.x);
            float tg0 = tanhf(pg0 + gg.x), og0 = sigf(po0 + go.x);
            float cn0 = (fg0 * creg0 + ig0 * tg0) * mk;
            float hn0 = og0 * tanhf(cn0) * mk;
            creg0 = cn0;

            float ig1 = sigf(pi1 + gi.y), fg1 = sigf(pF1 + gf.y);
            float tg1 = tanhf(pg1 + gg.y), og1 = sigf(po1 + go.y);
            float cn1 = (fg1 * creg1 + ig1 * tg1) * mk;
            float hn1 = og1 * tanhf(cn1) * mk;
            creg1 = cn1;

            float2 hv2 = make_float2(hn0, hn1);
            __stcg((float2*)&hout[b * HID + hcol0], hv2);
            __stcg((float2*)&outcat[(size_t)t * (BATCH * D2H) + (size_t)b * D2H
                                    + dir * HID + hcol0], hv2);
        }

        // ---- per-direction grid barrier ----
        __threadfence();
        __syncthreads();
        if (tid == 0) {
            atomicAdd(&g_bar[dir], 1u);
            const unsigned target = (unsigned)NBLK_DIR * (unsigned)(s + 1);
            volatile unsigned* pb = &g_bar[dir];
            while (*pb < target) __nanosleep(32);
        }
        __syncthreads();
    }

    // final c state (final h already in g_h[dir][0])
    if (kh == 0)
        *(float2*)&g_c[dir][b * HID + hcol0] = make_float2(creg0, creg1);
}

// ---------------- small state kernels ----------------
__global__ void init_states_kernel(const float* __restrict__ f_init,
                                   const float* __restrict__ b_init, int layer)
{
    int idx = blockIdx.x * blockDim.x + threadIdx.x;
    if (idx < 2 && blockIdx.x == 0) g_bar[idx] = 0;
    if (idx >= BATCH * HID) return;
    int j = idx & (HID - 1);
    const float* fi = f_init + layer * 2 * HID;
    const float* bi = b_init + layer * 2 * HID;
    g_h[0][0][idx] = fi[j];
    g_c[0][idx]    = fi[HID + j];
    g_h[1][0][idx] = bi[j];
    g_c[1][idx]    = bi[HID + j];
}

__global__ void copy_states_kernel(float* __restrict__ hn, float* __restrict__ cn, int layer)
{
    int idx = blockIdx.x * blockDim.x + threadIdx.x;
    if (idx >= BATCH * HID) return;
    hn[(size_t)(2 * layer + 0) * BATCH * HID + idx] = g_h[0][0][idx];
    hn[(size_t)(2 * layer + 1) * BATCH * HID + idx] = g_h[1][0][idx];
    cn[(size_t)(2 * layer + 0) * BATCH * HID + idx] = g_c[0][idx];
    cn[(size_t)(2 * layer + 1) * BATCH * HID + idx] = g_c[1][idx];
}

// ---------------- launcher ----------------
extern "C" void kernel_launch(void* const* d_in, const int* in_sizes, int n_in,
                              void* d_out, int out_size)
{
    const float* x          = (const float*)d_in[0];
    const float* masks      = (const float*)d_in[1];
    const float* f_Wih0     = (const float*)d_in[2];
    const float* f_Wih_rest = (const float*)d_in[3];
    const float* f_Whh      = (const float*)d_in[4];
    const float* f_b        = (const float*)d_in[5];
    const float* b_Wih0     = (const float*)d_in[6];
    const float* b_Wih_rest = (const float*)d_in[7];
    const float* b_Whh      = (const float*)d_in[8];
    const float* b_b        = (const float*)d_in[9];
    const float* f_init     = (const float*)d_in[10];
    const float* b_init     = (const float*)d_in[11];
    const float* proj_W     = (const float*)d_in[12];
    const float* proj_b     = (const float*)d_in[13];

    float* out = (float*)d_out;                       // [T,B,2H]
    float* hn  = out + (size_t)MR * D2H;              // [6,B,H]
    float* cn  = hn + (size_t)6 * BATCH * HID;        // [6,B,H]

    cudaFuncSetAttribute(pers_lstm_kernel,
                         cudaFuncAttributeMaxDynamicSharedMemorySize, PERS_SMEM_BYTES);

    const int layerInSel[3]  = { 0, 1, 3 };   // x, bufA, bufC
    const int catSel[3]      = { 1, 2, 1 };   // bufA, bufB, bufA
    const int Kin[3]         = { 512, 1024, 1024 };

    for (int layer = 0; layer < 3; layer++) {
        init_states_kernel<<<128, 256>>>(f_init, b_init, layer);

        const float* Wf = (layer == 0) ? f_Wih0 : f_Wih_rest + (size_t)(layer - 1) * G4H * D2H;
        const float* Wb = (layer == 0) ? b_Wih0 : b_Wih_rest + (size_t)(layer - 1) * G4H * D2H;
        dim3 ggrid(G4H / BNT, MR / BMT, 2);
        gemm_kernel<0><<<ggrid, 256>>>(
            (layer == 0) ? x : nullptr, layerInSel[layer],
            Wf, Wb,
            f_b + (size_t)layer * G4H, b_b + (size_t)layer * G4H,
            nullptr, 4 /*gxf*/, nullptr, 5 /*gxb*/,
            nullptr, 0,
            MR, G4H, Kin[layer]);

        const float* Whf = f_Whh + (size_t)layer * G4H * HID;
        const float* Whb = b_Whh + (size_t)layer * G4H * HID;
        pers_lstm_kernel<<<dim3(NBLK_DIR, 2), 512, PERS_SMEM_BYTES>>>(
            Whf, Whb, masks, f_init, b_init, layer, catSel[layer], nullptr);

        copy_states_kernel<<<128, 256>>>(hn, cn, layer);

        if (layer > 0) {
            dim3 pgrid(D2H / BNT, MR / BMT, 1);
            gemm_kernel<1><<<pgrid, 256>>>(
                nullptr, catSel[layer],
                proj_W + (size_t)(layer - 1) * D2H * D2H, nullptr,
                proj_b + (size_t)(layer - 1) * D2H, nullptr,
                (layer == 2) ? out : nullptr, (layer == 1) ? 3 : 0,
                nullptr, 0,
                nullptr, layerInSel[layer],
                MR, D2H, D2H);
        }
    }
}